// round 2
// baseline (speedup 1.0000x reference)
#include <cuda_runtime.h>
#include <stdint.h>

#define N_AA  20
#define NSEQ  2048
#define SLEN  512
#define MPOS  100

// Scratch (allocation-free rule: __device__ globals)
__device__ uint8_t g_msaT[SLEN * NSEQ];       // 1 MB, transposed msa as u8
__device__ float   g_log2tab[NSEQ + 1];       // log2(c) for integer counts

// ---------------------------------------------------------------- log2 table
__global__ void k_init_tab() {
    int i = blockIdx.x * blockDim.x + threadIdx.x;
    if (i <= NSEQ) g_log2tab[i] = (i == 0) ? 0.0f : log2f((float)i);
}

// ------------------------------------------------- transpose msa -> u8 [i][n]
__global__ void k_transpose(const int* __restrict__ msa) {
    __shared__ uint8_t tile[32][33];
    int i0 = blockIdx.x * 32;
    int n0 = blockIdx.y * 32;
    int tx = threadIdx.x, ty = threadIdx.y;
    tile[ty][tx] = (uint8_t)msa[(n0 + ty) * SLEN + (i0 + tx)];   // coalesced read
    __syncthreads();
    g_msaT[(size_t)(i0 + ty) * NSEQ + (n0 + tx)] = tile[tx][ty]; // coalesced write
}

// ------------------------------------- per-position counts -> pssm + conserv.
__global__ void k_stats(const float* __restrict__ pc,
                        float* __restrict__ out_pssm,
                        float* __restrict__ out_cons) {
    __shared__ int   hist[N_AA + 1];
    __shared__ float ent_terms[N_AA];
    __shared__ int   sh_total;
    int i   = blockIdx.x;
    int tid = threadIdx.x;
    if (tid <= N_AA) hist[tid] = 0;
    __syncthreads();

    // 2048 bytes / 256 threads = one uint2 (8 samples) per thread
    const uint2* col = (const uint2*)&g_msaT[(size_t)i * NSEQ];
    uint2 v = col[tid];
    #pragma unroll
    for (int b = 0; b < 4; b++) atomicAdd(&hist[(v.x >> (8 * b)) & 0xFF], 1);
    #pragma unroll
    for (int b = 0; b < 4; b++) atomicAdd(&hist[(v.y >> (8 * b)) & 0xFF], 1);
    __syncthreads();

    if (tid == 0) {
        int t = 0;
        #pragma unroll
        for (int a = 0; a < N_AA; a++) t += hist[a];
        sh_total = t;
    }
    __syncthreads();
    float pcv   = 0.01f * pc[0];
    int   total = sh_total;
    if (tid < N_AA) {
        float c    = (float)hist[tid];
        float freq = (c + pcv) / ((float)NSEQ + pcv * (float)N_AA);
        out_pssm[i * N_AA + tid] = logf(freq * (float)N_AA + 1e-10f);
        float f = c / fmaxf((float)total, 1.0f);
        ent_terms[tid] = f * log2f(f + 1e-10f);
    }
    __syncthreads();
    if (tid == 0) {
        float ent = 0.0f;
        #pragma unroll
        for (int a = 0; a < N_AA; a++) ent += ent_terms[a];
        ent = -ent;
        out_cons[i] = (total > 0) ? (1.0f - ent / 4.321928094887363f) : 0.0f;
    }
}

// -------------------------------------------------------- zero the MI canvas
__global__ void k_zero(float* __restrict__ p, int n) {
    int i = blockIdx.x * blockDim.x + threadIdx.x;
    if (i < n) p[i] = 0.0f;
}

// ------------------------------------------------- MI per unique pair (i<j)
__global__ void k_mi(float* __restrict__ out_mi) {
    int i = blockIdx.x, j = blockIdx.y;
    if (i >= j) return;                        // diagonal stays 0, mirror below

    __shared__ int   hist[N_AA * N_AA];
    __shared__ int   ci[N_AA], cj[N_AA];
    __shared__ float tci[N_AA], tcj[N_AA];
    __shared__ float sh_tabtot;
    __shared__ int   sh_tot;
    __shared__ float warp_red[8];

    int tid  = threadIdx.x;
    int lane = tid & 31;
    int wid  = tid >> 5;

    for (int k = tid; k < N_AA * N_AA; k += 256) hist[k] = 0;
    __syncthreads();

    // 2048 samples / 256 threads = 8 per thread; one uint2 load per column
    const uint2* colA = (const uint2*)&g_msaT[(size_t)i * NSEQ];
    const uint2* colB = (const uint2*)&g_msaT[(size_t)j * NSEQ];
    uint2 va = colA[tid];
    uint2 vb = colB[tid];
    #pragma unroll
    for (int b = 0; b < 4; b++) {
        int a0 = (va.x >> (8 * b)) & 0xFF, b0 = (vb.x >> (8 * b)) & 0xFF;
        if (a0 < N_AA && b0 < N_AA) atomicAdd(&hist[a0 * N_AA + b0], 1);
    }
    #pragma unroll
    for (int b = 0; b < 4; b++) {
        int a0 = (va.y >> (8 * b)) & 0xFF, b0 = (vb.y >> (8 * b)) & 0xFF;
        if (a0 < N_AA && b0 < N_AA) atomicAdd(&hist[a0 * N_AA + b0], 1);
    }
    __syncthreads();

    // marginals (two warps in parallel)
    if (tid < N_AA) {
        int s = 0;
        #pragma unroll
        for (int b = 0; b < N_AA; b++) s += hist[tid * N_AA + b];
        ci[tid] = s;
    } else if (tid >= 32 && tid < 32 + N_AA) {
        int t = tid - 32, s = 0;
        #pragma unroll
        for (int a = 0; a < N_AA; a++) s += hist[a * N_AA + t];
        cj[t] = s;
    }
    __syncthreads();

    if (tid < N_AA) {
        tci[tid] = g_log2tab[ci[tid]];
    } else if (tid >= 32 && tid < 32 + N_AA) {
        tcj[tid - 32] = g_log2tab[cj[tid - 32]];
    } else if (tid == 64) {
        int t = 0;
        #pragma unroll
        for (int a = 0; a < N_AA; a++) t += ci[a];
        sh_tot    = t;
        sh_tabtot = g_log2tab[t];
    }
    __syncthreads();

    // mi = (1/tot) * sum_{c>0} c * (log2 c + log2 tot - log2 ci - log2 cj)
    // kept as a per-bin log-difference (small terms) to avoid cancellation.
    float tabtot = sh_tabtot;
    float s = 0.0f;
    for (int k = tid; k < N_AA * N_AA; k += 256) {
        int c = hist[k];
        if (c > 0) {
            int a = k / N_AA, b = k - a * N_AA;
            s += (float)c * (g_log2tab[c] + tabtot - tci[a] - tcj[b]);
        }
    }
    // warp-shuffle reduction, then cross-warp via smem
    #pragma unroll
    for (int off = 16; off > 0; off >>= 1)
        s += __shfl_down_sync(0xFFFFFFFF, s, off);
    if (lane == 0) warp_red[wid] = s;
    __syncthreads();
    if (tid == 0) {
        float tot_s = 0.0f;
        #pragma unroll
        for (int w = 0; w < 8; w++) tot_s += warp_red[w];
        float mi = (sh_tot > 0) ? (tot_s / (float)sh_tot) : 0.0f;
        out_mi[i * SLEN + j] = mi;
        out_mi[j * SLEN + i] = mi;
    }
}

// ---------------------------------------------------------------------------
extern "C" void kernel_launch(void* const* d_in, const int* in_sizes, int n_in,
                              void* d_out, int out_size) {
    const int*   msa = nullptr;
    const float* pc  = nullptr;
    for (int k = 0; k < n_in; k++) {
        if (in_sizes[k] == NSEQ * SLEN) msa = (const int*)d_in[k];
        else if (in_sizes[k] == 1)      pc  = (const float*)d_in[k];
    }
    float* out      = (float*)d_out;
    float* out_pssm = out;                          // [512][20]
    float* out_cons = out + SLEN * N_AA;            // [512]
    float* out_mi   = out + SLEN * N_AA + SLEN;     // [512][512]

    k_init_tab<<<(NSEQ + 1 + 255) / 256, 256>>>();
    k_transpose<<<dim3(SLEN / 32, NSEQ / 32), dim3(32, 32)>>>(msa);
    k_stats<<<SLEN, 256>>>(pc, out_pssm, out_cons);
    k_zero<<<(SLEN * SLEN + 1023) / 1024, 1024>>>(out_mi, SLEN * SLEN);
    k_mi<<<dim3(MPOS, MPOS), 256>>>(out_mi);
}

// round 7
// speedup vs baseline: 1.2028x; 1.2028x over previous
#include <cuda_runtime.h>
#include <stdint.h>
#include <math.h>

#define N_AA   20
#define NSEQ   2048
#define SLEN   512
#define MPOS   100
#define NPAIR  (MPOS * (MPOS - 1) / 2)   // 4950 packed upper-triangle pairs
#define NBLK   (NPAIR + SLEN)            // + 512 stats/zero-role blocks

// Scratch (allocation-free rule: __device__ globals)
__device__ uint8_t g_msaT[SLEN * NSEQ];       // 1 MB, transposed msa as u8
__device__ float   g_log2tab[NSEQ + 1];       // log2(c) for integer counts

// -------------------- launch 1: transpose msa -> u8 [i][n], + log2 table ----
__global__ void k_transpose_init(const int* __restrict__ msa) {
    __shared__ uint8_t tile[32][33];
    int i0 = blockIdx.x * 32;
    int n0 = blockIdx.y * 32;
    int tx = threadIdx.x, ty = threadIdx.y;

    // fold log2-table init into the first 3 blocks of column 0
    if (blockIdx.x == 0 && blockIdx.y < 3) {
        int idx = blockIdx.y * 1024 + ty * 32 + tx;
        if (idx <= NSEQ) g_log2tab[idx] = (idx == 0) ? 0.0f : log2f((float)idx);
    }

    tile[ty][tx] = (uint8_t)msa[(n0 + ty) * SLEN + (i0 + tx)];   // coalesced read
    __syncthreads();
    g_msaT[(size_t)(i0 + ty) * NSEQ + (n0 + tx)] = tile[tx][ty]; // coalesced write
}

// -------------------- launch 2: everything else in one grid -----------------
__global__ void __launch_bounds__(256) k_main(const float* __restrict__ pc,
                                              float* __restrict__ out_pssm,
                                              float* __restrict__ out_cons,
                                              float* __restrict__ out_mi) {
    int bx  = blockIdx.x;
    int tid = threadIdx.x;

    if (bx >= NPAIR) {
        // ---------------- stats + zero-fill role: position r ----------------
        int r = bx - NPAIR;

        // zero the non-MI part of MI-canvas row r, and the diagonal cell
        {
            int    c0   = (r < MPOS) ? MPOS : 0;
            float4 z4   = make_float4(0.f, 0.f, 0.f, 0.f);
            float4* row = (float4*)(out_mi + r * SLEN + c0);
            int     n4  = (SLEN - c0) >> 2;
            for (int k = tid; k < n4; k += 256) row[k] = z4;
            if (tid == 0 && r < MPOS) out_mi[r * SLEN + r] = 0.0f;
        }

        __shared__ int   hist[N_AA + 1];
        __shared__ float ent_terms[N_AA];
        __shared__ int   sh_total;
        if (tid <= N_AA) hist[tid] = 0;
        __syncthreads();

        // 2048 samples / 256 threads = one uint2 (8 samples) per thread
        const uint2* col = (const uint2*)&g_msaT[(size_t)r * NSEQ];
        uint2 v = col[tid];
        #pragma unroll
        for (int b = 0; b < 4; b++) atomicAdd(&hist[(v.x >> (8 * b)) & 0xFF], 1);
        #pragma unroll
        for (int b = 0; b < 4; b++) atomicAdd(&hist[(v.y >> (8 * b)) & 0xFF], 1);
        __syncthreads();

        if (tid == 0) {
            int t = 0;
            #pragma unroll
            for (int a = 0; a < N_AA; a++) t += hist[a];
            sh_total = t;
        }
        __syncthreads();
        float pcv   = 0.01f * pc[0];
        int   total = sh_total;
        if (tid < N_AA) {
            float c    = (float)hist[tid];
            float freq = (c + pcv) / ((float)NSEQ + pcv * (float)N_AA);
            out_pssm[r * N_AA + tid] = logf(freq * (float)N_AA + 1e-10f);
            float f = c / fmaxf((float)total, 1.0f);
            ent_terms[tid] = f * log2f(f + 1e-10f);
        }
        __syncthreads();
        if (tid == 0) {
            float ent = 0.0f;
            #pragma unroll
            for (int a = 0; a < N_AA; a++) ent += ent_terms[a];
            out_cons[r] = (total > 0) ? (1.0f + ent / 4.321928094887363f) : 0.0f;
        }
        return;
    }

    // ---------------- MI pair role: decode packed upper-triangle ------------
    // t -> (i,j), 0 <= i < j < MPOS.  Closed-form + exact integer correction.
    int t = bx;
    int i = (int)((2.0f * MPOS - 1.0f
                   - sqrtf((2.0f * MPOS - 1.0f) * (2.0f * MPOS - 1.0f)
                           - 8.0f * (float)t)) * 0.5f);
    // row_start(i) = i*(2*MPOS-1-i)/2 ; correct fp rounding exactly
    while (i > 0 && t <  (i * (2 * MPOS - 1 - i)) / 2) i--;
    while (t >= ((i + 1) * (2 * MPOS - 2 - i)) / 2 + (i + 1)) i++;
    int j = t - (i * (2 * MPOS - 1 - i)) / 2 + i + 1;

    __shared__ int   hist[N_AA * N_AA];
    __shared__ int   ci[N_AA], cj[N_AA];
    __shared__ float tci[N_AA], tcj[N_AA];
    __shared__ float sh_tabtot;
    __shared__ int   sh_tot;
    __shared__ float warp_red[8];

    int lane = tid & 31;
    int wid  = tid >> 5;

    for (int k = tid; k < N_AA * N_AA; k += 256) hist[k] = 0;
    __syncthreads();

    // 2048 samples / 256 threads = 8 per thread; one uint2 load per column
    const uint2* colA = (const uint2*)&g_msaT[(size_t)i * NSEQ];
    const uint2* colB = (const uint2*)&g_msaT[(size_t)j * NSEQ];
    uint2 va = colA[tid];
    uint2 vb = colB[tid];
    #pragma unroll
    for (int b = 0; b < 4; b++) {
        int a0 = (va.x >> (8 * b)) & 0xFF, b0 = (vb.x >> (8 * b)) & 0xFF;
        if (a0 < N_AA && b0 < N_AA) atomicAdd(&hist[a0 * N_AA + b0], 1);
    }
    #pragma unroll
    for (int b = 0; b < 4; b++) {
        int a0 = (va.y >> (8 * b)) & 0xFF, b0 = (vb.y >> (8 * b)) & 0xFF;
        if (a0 < N_AA && b0 < N_AA) atomicAdd(&hist[a0 * N_AA + b0], 1);
    }
    __syncthreads();

    // marginals (two warps in parallel)
    if (tid < N_AA) {
        int s = 0;
        #pragma unroll
        for (int b = 0; b < N_AA; b++) s += hist[tid * N_AA + b];
        ci[tid] = s;
    } else if (tid >= 32 && tid < 32 + N_AA) {
        int u = tid - 32, s = 0;
        #pragma unroll
        for (int a = 0; a < N_AA; a++) s += hist[a * N_AA + u];
        cj[u] = s;
    }
    __syncthreads();

    if (tid < N_AA) {
        tci[tid] = g_log2tab[ci[tid]];
    } else if (tid >= 32 && tid < 32 + N_AA) {
        tcj[tid - 32] = g_log2tab[cj[tid - 32]];
    } else if (tid == 64) {
        int u = 0;
        #pragma unroll
        for (int a = 0; a < N_AA; a++) u += ci[a];
        sh_tot    = u;
        sh_tabtot = g_log2tab[u];
    }
    __syncthreads();

    // mi = (1/tot) * sum_{c>0} c * (log2 c + log2 tot - log2 ci - log2 cj)
    // per-bin log-difference keeps terms small (no catastrophic cancellation).
    float tabtot = sh_tabtot;
    float s = 0.0f;
    for (int k = tid; k < N_AA * N_AA; k += 256) {
        int c = hist[k];
        if (c > 0) {
            int a = k / N_AA, b = k - a * N_AA;
            s += (float)c * (g_log2tab[c] + tabtot - tci[a] - tcj[b]);
        }
    }
    #pragma unroll
    for (int off = 16; off > 0; off >>= 1)
        s += __shfl_down_sync(0xFFFFFFFF, s, off);
    if (lane == 0) warp_red[wid] = s;
    __syncthreads();
    if (tid == 0) {
        float tot_s = 0.0f;
        #pragma unroll
        for (int w = 0; w < 8; w++) tot_s += warp_red[w];
        float mi = (sh_tot > 0) ? (tot_s / (float)sh_tot) : 0.0f;
        out_mi[i * SLEN + j] = mi;
        out_mi[j * SLEN + i] = mi;
    }
}

// ---------------------------------------------------------------------------
extern "C" void kernel_launch(void* const* d_in, const int* in_sizes, int n_in,
                              void* d_out, int out_size) {
    const int*   msa = nullptr;
    const float* pc  = nullptr;
    for (int k = 0; k < n_in; k++) {
        if (in_sizes[k] == NSEQ * SLEN) msa = (const int*)d_in[k];
        else if (in_sizes[k] == 1)      pc  = (const float*)d_in[k];
    }
    float* out      = (float*)d_out;
    float* out_pssm = out;                          // [512][20]
    float* out_cons = out + SLEN * N_AA;            // [512]
    float* out_mi   = out + SLEN * N_AA + SLEN;     // [512][512]

    k_transpose_init<<<dim3(SLEN / 32, NSEQ / 32), dim3(32, 32)>>>(msa);
    k_main<<<NBLK, 256>>>(pc, out_pssm, out_cons, out_mi);
}